// round 13
// baseline (speedup 1.0000x reference)
#include <cuda_runtime.h>
#include <cstdint>
#include <cstddef>

#define BATCH     16384
#define DIM       64
#define NSTEPS    100
#define BPC       12                 // samples per CTA
#define TPB       768                // BPC * DIM threads
#define NPAIRS    2016               // upper-triangle pairs of 64x64
#define MROWF     68                 // padded M row (floats) within a sample
#define SSTR      4360               // per-sample M stride (4352 + 8 skew -> sh halves 16 banks apart)
#define NGROUP    ((BATCH + BPC - 1) / BPC)   // 1366 CTAs
#define NRW       144                // warp-round slots: 6 rounds * 24 warps
#define G2_TOT    (NRW * 16 * 16)    // float4 slots: 144 * 16 kq * 16 pp = 36864

typedef unsigned long long ull;

__device__ int g_idx[BATCH];
__device__ int g_perm[BATCH];
__device__ int g_pairs[NPAIRS];
__device__ __align__(16) float4 g_G2[G2_TOT];  // [rw][kq][pp]: 256B chunk per (rw,kq)

// ---------------- packed f32x2 helpers (sm_103a) ----------------
__device__ __forceinline__ ull pack2(float x, float y) {
    ull r; asm("mov.b64 %0, {%1, %2};" : "=l"(r) : "f"(x), "f"(y)); return r;
}
__device__ __forceinline__ void unpack2(ull v, float& x, float& y) {
    asm("mov.b64 {%0, %1}, %2;" : "=f"(x), "=f"(y) : "l"(v));
}
__device__ __forceinline__ ull ffma2(ull a, ull b, ull c) {
    ull d; asm("fma.rn.f32x2 %0, %1, %2, %3;" : "=l"(d) : "l"(a), "l"(b), "l"(c));
    return d;
}
__device__ __forceinline__ void group_bar(int b) {      // 64-thread named barrier
    asm volatile("bar.sync %0, 64;" :: "r"(b + 1) : "memory");
}

// ---------------- setup: idx + descending counting sort + pair table + G planes ----
__global__ void setup_kernel(const float* __restrict__ t, const float* __restrict__ G) {
    __shared__ int hist[NSTEPS];
    __shared__ int off[NSTEPS];
    const int tid = threadIdx.x;                   // 512 threads
    if (tid < NSTEPS) hist[tid] = 0;
    __syncthreads();
    for (int b = tid; b < BATCH; b += blockDim.x) {
        int ix = (int)truncf(100.0f * t[b]);       // trunc(n*t/T), T=1
        ix = min(max(ix, 0), NSTEPS - 1);
        g_idx[b] = ix;
        atomicAdd(&hist[ix], 1);
    }
    if (tid == 0) {                                // diagonal-major pair table
        int p = 0;
        for (int d = 1; d < DIM; ++d)
            for (int i = 0; i + d < DIM; ++i)
                g_pairs[p++] = (i << 8) | (i + d);
    }
    __syncthreads();
    if (tid == 0) {                                // descending bins: long jobs first
        int run = 0;
        for (int bin = NSTEPS - 1; bin >= 0; --bin) { off[bin] = run; run += hist[bin]; }
    }
    __syncthreads();
    for (int b = tid; b < BATCH; b += blockDim.x) {
        int pos = atomicAdd(&off[g_idx[b]], 1);
        g_perm[pos] = b;
    }
    // ---- G planes: slot = (rw*16 + kq)*16 + pp ; pair p = rw*16 + pp ----
    for (int slot = tid; slot < G2_TOT; slot += blockDim.x) {
        int pp  = slot & 15;
        int kqw = slot >> 4;
        int kq  = kqw & 15;
        int rw  = kqw >> 4;          // 0..143
        int p   = rw * 16 + pp;
        float4 v = make_float4(0.f, 0.f, 0.f, 0.f);
        if (p < NPAIRS) {
            int pr = g_pairs[p];
            int i = pr >> 8, j = pr & 255;
            v = *reinterpret_cast<const float4*>(G + ((i * DIM + j) * DIM + 4 * kq));
        }
        g_G2[slot] = v;
    }
}

// ---------------- half-register 64-dot ----------------
// Front half (cols 0..31) from registers, back half (cols 32..63) from smem.
// Contraction order identical to previous rounds (q = 0..15).
__device__ __forceinline__ float dot64h(const ulonglong2 (&Mreg)[8],
                                        const ulonglong2* __restrict__ Mhi,
                                        const ulonglong2* __restrict__ V8) {
    ull a0 = 0ull, a1 = 0ull;
    #pragma unroll
    for (int q = 0; q < 8; ++q) {
        ulonglong2 v = V8[q];                    // broadcast within b-group
        a0 = ffma2(Mreg[q].x, v.x, a0);
        a1 = ffma2(Mreg[q].y, v.y, a1);
    }
    #pragma unroll
    for (int q = 0; q < 8; ++q) {
        ulonglong2 m = Mhi[q];                   // LDS.128, conflict-free
        ulonglong2 v = V8[8 + q];
        a0 = ffma2(m.x, v.x, a0);
        a1 = ffma2(m.y, v.y, a1);
    }
    float x0, x1, z0, z1;
    unpack2(a0, x0, x1);
    unpack2(a1, z0, z1);
    return (x0 + x1) + (z0 + z1);
}

// select 8B half m (0..11) from 6 ulonglong2 (compile-time m)
#define DU(m) (((m) & 1) ? du[(m) >> 1].y : du[(m) >> 1].x)

// ---------------- main integration kernel ----------------
__global__ void __launch_bounds__(TPB)
sde_kernel(const float* __restrict__ y0,
           const float* __restrict__ dW,
           float* __restrict__ out)
{
    extern __shared__ __align__(16) float smem[];
    float* Msm  = smem;                        // [BPC samples][SSTR]
    float* vbuf = smem + BPC * SSTR;           // ping-pong [2][TPB]
    float* dw3  = vbuf + 2 * TPB;              // [16 kq][2 sh][24 floats]

    const int tid  = threadIdx.x;
    const int b    = tid >> 6;                 // dot-phase sample
    const int i    = tid & 63;                 // dot-phase row
    const int w    = tid >> 5;                 // mform warp id (0..23)
    const int lane = tid & 31;
    const int pp   = lane >> 1;                // pair sub-index in warp (0..15)
    const int sh   = lane & 1;                 // sample half (0: b0-5, 1: b6-11)

    int gidx = blockIdx.x * BPC + b;
    if (gidx >= BATCH) gidx = BATCH - 1;       // ghost -> duplicate last sample (benign)
    const int sb    = g_perm[gidx];
    const int myidx = g_idx[sb];
    const int smax  = g_idx[g_perm[blockIdx.x * BPC]];   // sorted desc -> first is max

    // mform pair offsets per round: p_r = (r*24 + w)*16 + pp  (round 5 only for w<6)
    const int nr = (w < 6) ? 6 : 5;
    int upo6[6], loo6[6];
    #pragma unroll
    for (int r = 0; r < 6; ++r) {
        int p  = (r * 24 + w) * 16 + pp;
        int pr = g_pairs[min(p, NPAIRS - 1)];
        int ii = pr >> 8, jj = pr & 255;
        upo6[r] = ii * MROWF + jj;
        loo6[r] = jj * MROWF + ii;
    }

    Msm[b * SSTR + i * MROWF + i] = 0.0f;      // diagonal exactly 0, set once

    float yr   = y0[sb * DIM + i];
    float r_dw = dW[(size_t)sb * DIM + i];     // dw(0)

    const ulonglong2* Mr  = reinterpret_cast<const ulonglong2*>(Msm + b * SSTR + i * MROWF);
    const ulonglong2* Mhi = Mr + 8;
    const ulonglong2* V0  = reinterpret_cast<const ulonglong2*>(vbuf + b * DIM);
    const ulonglong2* V1  = reinterpret_cast<const ulonglong2*>(vbuf + TPB + b * DIM);
    // dw3 base for this lane's sample half
    const ulonglong2* dwp = reinterpret_cast<const ulonglong2*>(dw3 + sh * 24);
    // dw3 staging slot for thread (b,i): kq=i>>2, kk=i&3, sh_w=b/6, sp=(b%6)>>1, comp=b&1
    const int stg = (i >> 2) * 48 + (b / 6) * 24 + (i & 3) * 6 + ((b % 6) >> 1) * 2 + (b & 1);

    for (int s = 0; s <= smax; ++s) {
        dw3[stg]  = r_dw;                      // stage dw(s), mform-ready layout
        vbuf[tid] = yr;                        // v0 = y
        __syncthreads();                       // barA: dw3/v0 ready; prior reads done

        r_dw = dW[((size_t)min(s + 1, NSTEPS - 1) * BATCH + sb) * DIM + i];  // prefetch

        // ---- M formation: warp = 16 pairs x 2 sample-halves ----
        ull acc[6][3];
        #pragma unroll
        for (int r = 0; r < 6; ++r)
            #pragma unroll
            for (int q = 0; q < 3; ++q) acc[r][q] = 0ull;

        #pragma unroll 4
        for (int kq = 0; kq < 16; ++kq) {
            ulonglong2 du[6];                  // 24 floats: [kk][3 sample-pairs]
            #pragma unroll
            for (int c = 0; c < 6; ++c) du[c] = dwp[kq * 12 + c];   // 12 ull2 per kq (both sh)
            const float4* gq = g_G2 + (size_t)kq * 16 + pp;
            #pragma unroll
            for (int r = 0; r < 5; ++r) {
                float4 g4 = __ldg(gq + (size_t)(r * 24 + w) * 256);
                #pragma unroll
                for (int kk = 0; kk < 4; ++kk) {
                    float gv = (kk == 0) ? g4.x : (kk == 1) ? g4.y : (kk == 2) ? g4.z : g4.w;
                    ull gg = pack2(gv, gv);
                    acc[r][0] = ffma2(gg, DU(kk * 3 + 0), acc[r][0]);
                    acc[r][1] = ffma2(gg, DU(kk * 3 + 1), acc[r][1]);
                    acc[r][2] = ffma2(gg, DU(kk * 3 + 2), acc[r][2]);
                }
            }
            if (w < 6) {                       // round 5: warps 0..5 only (pairs 1920..2015)
                float4 g4 = __ldg(gq + (size_t)(5 * 24 + w) * 256);
                #pragma unroll
                for (int kk = 0; kk < 4; ++kk) {
                    float gv = (kk == 0) ? g4.x : (kk == 1) ? g4.y : (kk == 2) ? g4.z : g4.w;
                    ull gg = pack2(gv, gv);
                    acc[5][0] = ffma2(gg, DU(kk * 3 + 0), acc[5][0]);
                    acc[5][1] = ffma2(gg, DU(kk * 3 + 1), acc[5][1]);
                    acc[5][2] = ffma2(gg, DU(kk * 3 + 2), acc[5][2]);
                }
            }
        }

        // ---- write both triangles (skew exact); conflict-free by construction ----
        {
            float* Mb = Msm + sh * 6 * SSTR;   // this lane's sample half
            #pragma unroll
            for (int r = 0; r < 6; ++r) {
                if (r < 5 || w < 6) {
                    float* up = Mb + upo6[r];
                    float* lo = Mb + loo6[r];
                    #pragma unroll
                    for (int q = 0; q < 3; ++q) {
                        float va, vb;
                        unpack2(acc[r][q], va, vb);
                        up[(2 * q + 0) * SSTR] =  va;  lo[(2 * q + 0) * SSTR] = -va;
                        up[(2 * q + 1) * SSTR] =  vb;  lo[(2 * q + 1) * SSTR] = -vb;
                    }
                }
            }
        }
        __syncthreads();                       // barB: M(s) complete & visible

        // Front half of my M row into registers; reused by all 4 stages.
        ulonglong2 Mreg[8];
        #pragma unroll
        for (int q = 0; q < 8; ++q) Mreg[q] = Mr[q];

        // ---- RK4 stages; per-sample 64-thread named barriers ----
        float u1 = dot64h(Mreg, Mhi, V0);
        vbuf[TPB + tid] = yr + 0.5f * u1;
        group_bar(b);

        float u2 = dot64h(Mreg, Mhi, V1);
        vbuf[tid] = yr + 0.5f * u2;
        group_bar(b);

        float u3 = dot64h(Mreg, Mhi, V0);
        vbuf[TPB + tid] = yr + u3;
        group_bar(b);

        float u4 = dot64h(Mreg, Mhi, V1);
        yr += (u1 + 2.0f * u2 + 2.0f * u3 + u4) / 6.0f;

        if (s == myidx) out[sb * DIM + i] = yr;            // fused ys[idx_b] gather
        // loop-top barA covers WAR on dw3/vbuf/Msm for next step
    }
}

// ---------------- launch ----------------
extern "C" void kernel_launch(void* const* d_in, const int* in_sizes, int n_in,
                              void* d_out, int out_size) {
    const float* y0 = nullptr;
    const float* t  = nullptr;
    const float* G  = nullptr;
    const float* dW = nullptr;
    for (int k = 0; k < n_in; ++k) {           // robust size-based remap
        const float* p = (const float*)d_in[k];
        long sz = in_sizes[k];
        if      (sz == BATCH)                      t  = p;
        else if (sz == BATCH * DIM)                y0 = p;
        else if (sz == DIM * DIM * DIM)            G  = p;
        else if (sz == (long)NSTEPS * BATCH * DIM) dW = p;
    }
    float* out = (float*)d_out;

    const size_t smem_bytes =
        (size_t)(BPC * SSTR + 2 * TPB + 16 * 48) * sizeof(float);   // 218,496 B
    cudaFuncSetAttribute(sde_kernel, cudaFuncAttributeMaxDynamicSharedMemorySize,
                         (int)smem_bytes);

    setup_kernel<<<1, 512>>>(t, G);
    sde_kernel<<<NGROUP, TPB, smem_bytes>>>(y0, dW, out);
}

// round 14
// speedup vs baseline: 1.2631x; 1.2631x over previous
#include <cuda_runtime.h>
#include <cstdint>
#include <cstddef>

#define BATCH     16384
#define DIM       64
#define NSTEPS    100
#define BPC       12                // samples per CTA (smem ceiling)
#define TPB       768               // BPC * DIM threads
#define NPAIRS    2016              // upper-triangle pairs of 64x64
#define NPAIR_TOT 2048              // 512 threads * 3 pairs + 256 threads * 2 pairs
#define MROWF     68                // padded M row (floats): conflict-free LDS.128
#define MSAMP     (DIM * MROWF)     // 4352 floats per per-sample M
#define NGROUP    ((BATCH + BPC - 1) / BPC)   // 1366 CTAs
#define GQ_TOT    32768             // float4 slots: 2048 pairs * 16 kq

typedef unsigned long long ull;

__device__ int g_idx[BATCH];
__device__ int g_perm[BATCH];
__device__ int g_pairs[NPAIR_TOT];
__device__ __align__(16) float4 g_GQ[GQ_TOT];   // tierA: [c][kq][512]; tierB @24576: [c][kq][256]

// ---------------- packed f32x2 helpers (sm_103a) ----------------
__device__ __forceinline__ ull pack2(float x, float y) {
    ull r; asm("mov.b64 %0, {%1, %2};" : "=l"(r) : "f"(x), "f"(y)); return r;
}
__device__ __forceinline__ void unpack2(ull v, float& x, float& y) {
    asm("mov.b64 {%0, %1}, %2;" : "=f"(x), "=f"(y) : "l"(v));
}
__device__ __forceinline__ ull ffma2(ull a, ull b, ull c) {
    ull d; asm("fma.rn.f32x2 %0, %1, %2, %3;" : "=l"(d) : "l"(a), "l"(b), "l"(c));
    return d;
}
__device__ __forceinline__ void group_bar(int b) {      // 64-thread named barrier
    asm volatile("bar.sync %0, 64;" :: "r"(b + 1) : "memory");
}

// ---------------- setup: idx + descending counting sort + pair table + G planes ----
__global__ void setup_kernel(const float* __restrict__ t, const float* __restrict__ G) {
    __shared__ int hist[NSTEPS];
    __shared__ int off[NSTEPS];
    const int tid = threadIdx.x;                   // 512 threads
    if (tid < NSTEPS) hist[tid] = 0;
    __syncthreads();
    for (int b = tid; b < BATCH; b += blockDim.x) {
        int ix = (int)truncf(100.0f * t[b]);       // trunc(n*t/T), T=1
        ix = min(max(ix, 0), NSTEPS - 1);
        g_idx[b] = ix;
        atomicAdd(&hist[ix], 1);
    }
    if (tid == 0) {                                // pair table (i<j), pad with (0,0)
        int p = 0;
        for (int i = 0; i < DIM; ++i)
            for (int j = i + 1; j < DIM; ++j)
                g_pairs[p++] = (i << 8) | j;
        for (; p < NPAIR_TOT; ++p) g_pairs[p] = 0;
    }
    __syncthreads();
    if (tid == 0) {                                // descending bins: long jobs first
        int run = 0;
        for (int bin = NSTEPS - 1; bin >= 0; --bin) { off[bin] = run; run += hist[bin]; }
    }
    __syncthreads();
    for (int b = tid; b < BATCH; b += blockDim.x) {
        int pos = atomicAdd(&off[g_idx[b]], 1);
        g_perm[pos] = b;
    }
    // ---- G planes ----
    // tierA slot = (c*16+kq)*512 + t        (t in [0,512), c in [0,3))  -> pair 3t+c
    // tierB slot = 24576 + (c*16+kq)*256+tb (tb in [0,256), c in [0,2)) -> pair 1536+2tb+c
    for (int gid = tid; gid < GQ_TOT; gid += blockDim.x) {
        int c, kq, p;
        if (gid < 24576) {
            c = gid >> 13; int r = gid & 8191; kq = r >> 9; int tt = r & 511;
            p = 3 * tt + c;
        } else {
            int g2 = gid - 24576;
            c = g2 >> 12; int r = g2 & 4095; kq = r >> 8; int tb = r & 255;
            p = 1536 + 2 * tb + c;
        }
        float4 v = make_float4(0.f, 0.f, 0.f, 0.f);
        if (p < NPAIRS) {
            int pr = g_pairs[p];
            int i = pr >> 8, j = pr & 255;
            v = *reinterpret_cast<const float4*>(G + ((i * DIM + j) * DIM + 4 * kq));
        }
        g_GQ[gid] = v;
    }
}

// ---------------- full M-formation: all 16 kq-groups, acc in registers ----------------
template<int PC>
__device__ __forceinline__ void mform_full(const float4* __restrict__ gp, int gstride,
                                           const float* __restrict__ dwc,
                                           ull (&acc)[3][6]) {
    #pragma unroll 4
    for (int kq = 0; kq < 16; ++kq) {
        float4 g[PC];
        #pragma unroll
        for (int c = 0; c < PC; ++c)
            g[c] = __ldg(gp + (c * 16 + kq) * gstride);
        #pragma unroll
        for (int kk = 0; kk < 4; ++kk) {
            const ulonglong2* w =
                reinterpret_cast<const ulonglong2*>(dwc + (4 * kq + kk) * BPC);
            ulonglong2 wa = w[0], wb = w[1], wc = w[2];   // 12 samples, broadcast LDS
            #pragma unroll
            for (int c = 0; c < PC; ++c) {
                float gv = (kk == 0) ? g[c].x : (kk == 1) ? g[c].y
                         : (kk == 2) ? g[c].z : g[c].w;
                ull gg = pack2(gv, gv);
                acc[c][0] = ffma2(gg, wa.x, acc[c][0]);
                acc[c][1] = ffma2(gg, wa.y, acc[c][1]);
                acc[c][2] = ffma2(gg, wb.x, acc[c][2]);
                acc[c][3] = ffma2(gg, wb.y, acc[c][3]);
                acc[c][4] = ffma2(gg, wc.x, acc[c][4]);
                acc[c][5] = ffma2(gg, wc.y, acc[c][5]);
            }
        }
    }
}

template<int PC>
__device__ __forceinline__ void mwrite(float* __restrict__ Mb,
                                       const int* upo, const int* loo, int nvalid,
                                       ull (&acc)[3][6]) {
    #pragma unroll
    for (int c = 0; c < PC; ++c) {
        if (c < nvalid) {
            float* up = Mb + upo[c];
            float* lo = Mb + loo[c];
            #pragma unroll
            for (int q = 0; q < 6; ++q) {
                float va, vb;
                unpack2(acc[c][q], va, vb);
                up[(2 * q + 0) * MSAMP] =  va;  lo[(2 * q + 0) * MSAMP] = -va;
                up[(2 * q + 1) * MSAMP] =  vb;  lo[(2 * q + 1) * MSAMP] = -vb;
            }
        }
    }
}

// ---------------- full-register 64-dot ----------------
// Entire M row in registers; only v comes from smem (broadcast within b-group).
// Contraction order identical to previous rounds (q = 0..15, .x->a0, .y->a1).
__device__ __forceinline__ float dot64r(const ulonglong2 (&M)[16],
                                        const ulonglong2* __restrict__ V8) {
    ull a0 = 0ull, a1 = 0ull;
    #pragma unroll
    for (int q = 0; q < 16; ++q) {
        ulonglong2 v = V8[q];                    // broadcast
        a0 = ffma2(M[q].x, v.x, a0);
        a1 = ffma2(M[q].y, v.y, a1);
    }
    float x0, x1, z0, z1;
    unpack2(a0, x0, x1);
    unpack2(a1, z0, z1);
    return (x0 + x1) + (z0 + z1);
}

// ---------------- main integration kernel ----------------
__global__ void __launch_bounds__(TPB)
sde_kernel(const float* __restrict__ y0,
           const float* __restrict__ dW,
           float* __restrict__ out)
{
    extern __shared__ __align__(16) float smem[];
    float* Msm  = smem;                        // [BPC][64][MROWF]
    float* vbuf = smem + BPC * MSAMP;          // ping-pong [2][TPB]
    float* dwT  = vbuf + 2 * TPB;              // [64][BPC]

    const int tid = threadIdx.x;
    const int b   = tid >> 6;
    const int i   = tid & 63;
    const bool tA = (tid < 512);

    int gidx = blockIdx.x * BPC + b;
    if (gidx >= BATCH) gidx = BATCH - 1;       // ghost -> duplicate last sample (benign)
    const int sb    = g_perm[gidx];
    const int myidx = g_idx[sb];
    const int smax  = g_idx[g_perm[blockIdx.x * BPC]];   // sorted desc -> first is max

    const int pbase = tA ? 3 * tid : 1536 + 2 * (tid - 512);
    int upo[3], loo[3];
    #pragma unroll
    for (int c = 0; c < 3; ++c) {
        int pr = g_pairs[min(pbase + c, NPAIR_TOT - 1)];
        int ii = pr >> 8, jj = pr & 255;
        upo[c] = ii * MROWF + jj;
        loo[c] = jj * MROWF + ii;
    }
    const int nvalid = min(tA ? 3 : 2, max(0, NPAIRS - pbase));

    const float4* gp  = tA ? (g_GQ + tid) : (g_GQ + 24576 + (tid - 512));
    const int gstride = tA ? 512 : 256;

    Msm[b * MSAMP + i * MROWF + i] = 0.0f;     // diagonal exactly 0, set once

    float yr   = y0[sb * DIM + i];
    float r_dw = dW[(size_t)sb * DIM + i];     // dw(0)

    const ulonglong2* Mr = reinterpret_cast<const ulonglong2*>(Msm + b * MSAMP + i * MROWF);
    const ulonglong2* V0 = reinterpret_cast<const ulonglong2*>(vbuf + b * DIM);
    const ulonglong2* V1 = reinterpret_cast<const ulonglong2*>(vbuf + TPB + b * DIM);

    for (int s = 0; s <= smax; ++s) {
        dwT[i * BPC + b] = r_dw;               // stage dw(s) transposed [k][b]
        vbuf[tid] = yr;                        // v0 = y
        __syncthreads();                       // barA: dwT/v0 ready; prior M/dwT reads done

        r_dw = dW[((size_t)min(s + 1, NSTEPS - 1) * BATCH + sb) * DIM + i];  // prefetch

        ull acc[3][6];
        #pragma unroll
        for (int c = 0; c < 3; ++c)
            #pragma unroll
            for (int q = 0; q < 6; ++q) acc[c][q] = 0ull;

        if (tA) { mform_full<3>(gp, gstride, dwT, acc); mwrite<3>(Msm, upo, loo, nvalid, acc); }
        else    { mform_full<2>(gp, gstride, dwT, acc); mwrite<2>(Msm, upo, loo, nvalid, acc); }
        __syncthreads();                       // barB: M(s) complete & visible

        // Load my ENTIRE M row into registers (16 conflict-free LDS.128);
        // all 4 RK4 stages then touch smem only for the v broadcasts.
        ulonglong2 Mrow[16];
        #pragma unroll
        for (int q = 0; q < 16; ++q) Mrow[q] = Mr[q];

        // ---- RK4 stages; per-sample 64-thread named barriers (no block convoy) ----
        float u1 = dot64r(Mrow, V0);
        vbuf[TPB + tid] = yr + 0.5f * u1;
        group_bar(b);

        float u2 = dot64r(Mrow, V1);
        vbuf[tid] = yr + 0.5f * u2;
        group_bar(b);

        float u3 = dot64r(Mrow, V0);
        vbuf[TPB + tid] = yr + u3;
        group_bar(b);

        float u4 = dot64r(Mrow, V1);
        yr += (u1 + 2.0f * u2 + 2.0f * u3 + u4) / 6.0f;

        if (s == myidx) out[sb * DIM + i] = yr;            // fused ys[idx_b] gather
        // loop-top barA covers WAR on dwT/vbuf/Msm for next step
    }
}

// ---------------- launch ----------------
extern "C" void kernel_launch(void* const* d_in, const int* in_sizes, int n_in,
                              void* d_out, int out_size) {
    const float* y0 = nullptr;
    const float* t  = nullptr;
    const float* G  = nullptr;
    const float* dW = nullptr;
    for (int k = 0; k < n_in; ++k) {           // robust size-based remap
        const float* p = (const float*)d_in[k];
        long sz = in_sizes[k];
        if      (sz == BATCH)                      t  = p;
        else if (sz == BATCH * DIM)                y0 = p;
        else if (sz == DIM * DIM * DIM)            G  = p;
        else if (sz == (long)NSTEPS * BATCH * DIM) dW = p;
    }
    float* out = (float*)d_out;

    const size_t smem_bytes =
        (size_t)(BPC * MSAMP + 2 * TPB + DIM * BPC) * sizeof(float);   // 218112 B
    cudaFuncSetAttribute(sde_kernel, cudaFuncAttributeMaxDynamicSharedMemorySize,
                         (int)smem_bytes);

    setup_kernel<<<1, 512>>>(t, G);
    sde_kernel<<<NGROUP, TPB, smem_bytes>>>(y0, dW, out);
}